// round 9
// baseline (speedup 1.0000x reference)
#include <cuda_runtime.h>
#include <cuda_fp16.h>
#include <cstdint>

// ---------------------------------------------------------------------------
// Fused ExtractorMLP, raw mma.sync.m16n8k16 (fp16 in, fp32 acc).
// Round 9: layer-2 A operands taken DIRECTLY from layer-1 accumulators.
// m16n8 C-fragment layout == m16k16 A-fragment sub-layout, so two adjacent n8
// acc tiles (relu'd, packed half2 in regs) form a layer-2 A fragment with no
// smem round-trip. Warp grid 8(M)x2(N): each warp owns a 64-wide x1 k-slice
// and accumulates a full-width (128N) layer-2 partial; the two k-halves merge
// through one smem exchange at the end. Main loop has ZERO barriers.
// ---------------------------------------------------------------------------

#define M_TILE  128
#define THREADS 512
#define LDF 264          // f12 leading dim (halves): 528B stride, mod128=16
#define SZ_F12 (M_TILE * LDF * 2)
#define SMEM_DYN SZ_F12
#define LDB 132          // epilogue exchange buffer leading dim (floats)

// fragment-packed weights (B operand order for mma.m16n8k16):
// g_W1F[s][p][lane]: s = k16-step (16), p = n16-pair (32), uint4 per lane.
__device__ uint4 g_W1F[16 * 32 * 32];   // 256 KB
__device__ uint4 g_W2F[32 * 8 * 32];    // 128 KB

__device__ __forceinline__ uint32_t pk2f(float a, float b) {
    __half2 h = __floats2half2_rn(a, b);
    return *reinterpret_cast<uint32_t*>(&h);
}

__global__ void prep_weights(const float* __restrict__ W1,
                             const float* __restrict__ W2) {
    int j = blockIdx.x * blockDim.x + threadIdx.x;
    if (j < 16 * 32 * 32) {
        int s    = j >> 10;
        int p    = (j >> 5) & 31;
        int lane = j & 31;
        int k0 = s * 16 + (lane & 3) * 2;
        int n0 = p * 16 + (lane >> 2);
        uint4 v;
        v.x = pk2f(W1[k0 * 512 + n0],           W1[(k0 + 1) * 512 + n0]);
        v.y = pk2f(W1[(k0 + 8) * 512 + n0],     W1[(k0 + 9) * 512 + n0]);
        v.z = pk2f(W1[k0 * 512 + n0 + 8],       W1[(k0 + 1) * 512 + n0 + 8]);
        v.w = pk2f(W1[(k0 + 8) * 512 + n0 + 8], W1[(k0 + 9) * 512 + n0 + 8]);
        g_W1F[j] = v;
    } else {
        int j2 = j - 16 * 32 * 32;
        if (j2 < 32 * 8 * 32) {
            int S    = j2 >> 8;
            int q    = (j2 >> 5) & 7;
            int lane = j2 & 31;
            int k0 = S * 16 + (lane & 3) * 2;
            int n0 = q * 16 + (lane >> 2);
            uint4 v;
            v.x = pk2f(W2[k0 * 128 + n0],           W2[(k0 + 1) * 128 + n0]);
            v.y = pk2f(W2[(k0 + 8) * 128 + n0],     W2[(k0 + 9) * 128 + n0]);
            v.z = pk2f(W2[k0 * 128 + n0 + 8],       W2[(k0 + 1) * 128 + n0 + 8]);
            v.w = pk2f(W2[(k0 + 8) * 128 + n0 + 8], W2[(k0 + 9) * 128 + n0 + 8]);
            g_W2F[j2] = v;
        }
    }
}

__device__ __forceinline__ void ldsm_x4(uint32_t r[4], const __half* p) {
    uint32_t addr = (uint32_t)__cvta_generic_to_shared(p);
    asm volatile("ldmatrix.sync.aligned.m8n8.x4.shared.b16 {%0,%1,%2,%3}, [%4];"
                 : "=r"(r[0]), "=r"(r[1]), "=r"(r[2]), "=r"(r[3])
                 : "r"(addr));
}

__device__ __forceinline__ void mma16816(float c[4], const uint32_t a[4],
                                         uint32_t b0, uint32_t b1) {
    asm volatile(
        "mma.sync.aligned.m16n8k16.row.col.f32.f16.f16.f32 "
        "{%0,%1,%2,%3}, {%4,%5,%6,%7}, {%8,%9}, {%0,%1,%2,%3};"
        : "+f"(c[0]), "+f"(c[1]), "+f"(c[2]), "+f"(c[3])
        : "r"(a[0]), "r"(a[1]), "r"(a[2]), "r"(a[3]), "r"(b0), "r"(b1));
}

__global__ void __launch_bounds__(THREADS, 1)
extractor_mlp_kernel(const float* __restrict__ emb,
                     const int* __restrict__ edge_index,
                     const float* __restrict__ b1,
                     const float* __restrict__ b2,
                     const float* __restrict__ W3,
                     const float* __restrict__ b3,
                     float* __restrict__ out, int E)
{
    extern __shared__ char smem[];
    __half* f12  = (__half*)smem;                 // [128][LDF]
    float*  xbuf = (float*)smem;                  // epilogue alias [128][LDB]

    __shared__ int   s_col[M_TILE];
    __shared__ int   s_row[M_TILE];
    __shared__ float b1s[512];
    __shared__ float b2s[128];
    __shared__ float W3s[128];

    const int tid  = threadIdx.x;
    const int lane = tid & 31;
    const int w    = tid >> 5;        // 0..15
    const int mg   = w & 7;           // M group: rows mg*16 .. +16
    const int ng   = w >> 3;          // k-half for layer 2 (0 or 1)
    const int base = blockIdx.x * M_TILE;

    // ---- indices + biases ------------------------------------------------
    if (tid < M_TILE) {
        int e = base + tid;
        s_col[tid] = (e < E) ? edge_index[e] : 0;
        s_row[tid] = (e < E) ? edge_index[E + e] : 0;
    } else if (tid < 2 * M_TILE) {
        int n = tid - M_TILE;
        b2s[n] = b2[n];
        W3s[n] = W3[n];
    }
    b1s[tid] = b1[tid];
    __syncthreads();

    // ---- gather f12 = [emb[col] | emb[row]] as half ------------------------
    for (int i = tid; i < M_TILE * 64; i += THREADS) {
        int m = i >> 6;
        int q = i & 63;
        int idx = (q < 32) ? s_col[m] : s_row[m];
        int qq  = (q < 32) ? q : (q - 32);
        float4 v = ((const float4*)(emb + (long long)idx * 128))[qq];
        uint32_t* dst = (uint32_t*)(f12 + m * LDF + q * 4);
        dst[0] = pk2f(v.x, v.y);
        dst[1] = pk2f(v.z, v.w);
    }
    __syncthreads();

    const int g  = lane >> 2;          // acc row group
    const int cp = (lane & 3) * 2;     // acc col pair base
    const __half* arow = f12 + (mg * 16 + (lane & 15)) * LDF + (lane >> 4) * 8;

    float acc2[16][4];                 // 16M x 128N layer-2 partial
    #pragma unroll
    for (int t = 0; t < 16; ++t)
        #pragma unroll
        for (int r = 0; r < 4; ++r)
            acc2[t][r] = 0.0f;

    #pragma unroll 1
    for (int c = 0; c < 4; ++c) {
        // ----- layer 1: acc1 = f12 @ W1[:, c*128 + ng*64 .. +64] ------------
        float acc1[8][4];
        #pragma unroll
        for (int t = 0; t < 8; ++t)
            #pragma unroll
            for (int r = 0; r < 4; ++r)
                acc1[t][r] = 0.0f;

        const int pbase = c * 8 + ng * 4;       // n16-pair base in W1F
        #pragma unroll 2
        for (int ks = 0; ks < 16; ++ks) {
            uint32_t a[4];
            ldsm_x4(a, arow + ks * 16);
            #pragma unroll
            for (int j = 0; j < 4; ++j) {
                uint4 B = g_W1F[(ks * 32 + pbase + j) * 32 + lane];
                mma16816(acc1[2 * j],     a, B.x, B.y);
                mma16816(acc1[2 * j + 1], a, B.z, B.w);
            }
        }

        // ----- bias+relu in regs, pack acc1 -> layer-2 A fragments ----------
        uint32_t Ah[4][4];                       // [k16-step][4 regs]
        #pragma unroll
        for (int t = 0; t < 8; ++t) {
            int col = c * 128 + ng * 64 + t * 8 + cp;
            float bx = b1s[col], by = b1s[col + 1];
            float r0 = fmaxf(acc1[t][0] + bx, 0.0f);
            float r1 = fmaxf(acc1[t][1] + by, 0.0f);
            float r2 = fmaxf(acc1[t][2] + bx, 0.0f);
            float r3 = fmaxf(acc1[t][3] + by, 0.0f);
            int kk = t >> 1;
            int o  = (t & 1) * 2;
            Ah[kk][o]     = pk2f(r0, r1);        // rows g   / g+8 pair
            Ah[kk][o + 1] = pk2f(r2, r3);
        }

        // ----- layer 2: acc2 += x1_slice @ W2[slice, :] (A from registers) --
        #pragma unroll
        for (int kk = 0; kk < 4; ++kk) {
            int S = c * 8 + ng * 4 + kk;         // global k16-step of W2
            #pragma unroll
            for (int q = 0; q < 8; ++q) {
                uint4 C = g_W2F[(S * 8 + q) * 32 + lane];
                mma16816(acc2[2 * q],     Ah[kk], C.x, C.y);
                mma16816(acc2[2 * q + 1], Ah[kk], C.z, C.w);
            }
        }
    }

    // ---- epilogue: merge the two k-half partials, then relu + W3 dot ------
    __syncthreads();                   // all f12 reads done; reuse as xbuf
    if (ng == 1) {
        #pragma unroll
        for (int t = 0; t < 16; ++t) {
            int col = t * 8 + cp;
            int r0  = mg * 16 + g;
            xbuf[r0 * LDB + col]           = acc2[t][0];
            xbuf[r0 * LDB + col + 1]       = acc2[t][1];
            xbuf[(r0 + 8) * LDB + col]     = acc2[t][2];
            xbuf[(r0 + 8) * LDB + col + 1] = acc2[t][3];
        }
    }
    __syncthreads();
    if (ng == 0) {
        float sA = 0.0f, sB = 0.0f;
        int r0 = mg * 16 + g;
        #pragma unroll
        for (int t = 0; t < 16; ++t) {
            int col = t * 8 + cp;
            float bx = b2s[col],     wx = W3s[col];
            float by = b2s[col + 1], wy = W3s[col + 1];
            float v0 = acc2[t][0] + xbuf[r0 * LDB + col];
            float v1 = acc2[t][1] + xbuf[r0 * LDB + col + 1];
            float v2 = acc2[t][2] + xbuf[(r0 + 8) * LDB + col];
            float v3 = acc2[t][3] + xbuf[(r0 + 8) * LDB + col + 1];
            sA += fmaxf(v0 + bx, 0.0f) * wx + fmaxf(v1 + by, 0.0f) * wy;
            sB += fmaxf(v2 + bx, 0.0f) * wx + fmaxf(v3 + by, 0.0f) * wy;
        }
        sA += __shfl_xor_sync(0xffffffffu, sA, 1);
        sA += __shfl_xor_sync(0xffffffffu, sA, 2);
        sB += __shfl_xor_sync(0xffffffffu, sB, 1);
        sB += __shfl_xor_sync(0xffffffffu, sB, 2);
        if ((lane & 3) == 0) {
            float bb = __ldg(b3);
            int eA = base + r0;
            int eB = base + r0 + 8;
            if (eA < E) out[eA] = sA + bb;
            if (eB < E) out[eB] = sB + bb;
        }
    }
}

extern "C" void kernel_launch(void* const* d_in, const int* in_sizes, int n_in,
                              void* d_out, int out_size)
{
    const float* emb = (const float*)d_in[0];
    const int*   ei  = (const int*)d_in[1];     // int32 (JAX x64 disabled)
    const float* W1  = (const float*)d_in[2];
    const float* b1  = (const float*)d_in[3];
    const float* W2  = (const float*)d_in[4];
    const float* b2  = (const float*)d_in[5];
    const float* W3  = (const float*)d_in[6];
    const float* b3  = (const float*)d_in[7];
    float* out = (float*)d_out;

    const int E = out_size;   // output is [E,1] float32

    prep_weights<<<(16*32*32 + 32*8*32 + 255) / 256, 256>>>(W1, W2);

    cudaFuncSetAttribute(extractor_mlp_kernel,
                         cudaFuncAttributeMaxDynamicSharedMemorySize, SMEM_DYN);

    int grid = (E + M_TILE - 1) / M_TILE;
    extractor_mlp_kernel<<<grid, THREADS, SMEM_DYN>>>(
        emb, ei, b1, b2, W3, b3, out, E);
}

// round 10
// speedup vs baseline: 1.4626x; 1.4626x over previous
#include <cuda_runtime.h>
#include <cuda_fp16.h>
#include <cstdint>

// ---------------------------------------------------------------------------
// Fused ExtractorMLP, raw mma.sync.m16n8k16 (fp16 in, fp32 acc).
// Round 10 = round-8 structure (16 warps, Mg=4 x Ng=4, warp tile 32x32) plus:
//   - emb pre-converted to half in prep (gather bytes halved, no cvt in loop)
//   - double-buffered x1h -> 1 barrier per chunk instead of 2
//   - software-pipelined B-fragment loads (prefetch ks+1 ahead of MMAs)
// ---------------------------------------------------------------------------

#define M_TILE  128
#define THREADS 512
#define LDF 264          // f12 leading dim (halves): 528B stride, mod128=16
#define LDX 136          // x1h leading dim (halves): 272B stride, mod128=16
#define SZ_F12 (M_TILE * LDF * 2)
#define SZ_X1H (M_TILE * LDX * 2)
#define SMEM_DYN (SZ_F12 + 2 * SZ_X1H)

#define N_NODES_MAX 50000

__device__ __half g_embh[N_NODES_MAX * 128];   // 12.8 MB
// fragment-packed weights (B operand order for mma.m16n8k16)
__device__ uint4 g_W1F[16 * 32 * 32];   // 256 KB
__device__ uint4 g_W2F[32 * 8 * 32];    // 128 KB

__device__ __forceinline__ uint32_t pk2f(float a, float b) {
    __half2 h = __floats2half2_rn(a, b);
    return *reinterpret_cast<uint32_t*>(&h);
}

__global__ void prep_emb(const float* __restrict__ emb, int n4) {
    int i = blockIdx.x * blockDim.x + threadIdx.x;   // one float4 -> 4 halves
    if (i < n4) {
        float4 v = ((const float4*)emb)[i];
        uint2 o;
        o.x = pk2f(v.x, v.y);
        o.y = pk2f(v.z, v.w);
        ((uint2*)g_embh)[i] = o;
    }
}

__global__ void prep_weights(const float* __restrict__ W1,
                             const float* __restrict__ W2) {
    int j = blockIdx.x * blockDim.x + threadIdx.x;
    if (j < 16 * 32 * 32) {
        int s    = j >> 10;
        int p    = (j >> 5) & 31;
        int lane = j & 31;
        int k0 = s * 16 + (lane & 3) * 2;
        int n0 = p * 16 + (lane >> 2);
        uint4 v;
        v.x = pk2f(W1[k0 * 512 + n0],           W1[(k0 + 1) * 512 + n0]);
        v.y = pk2f(W1[(k0 + 8) * 512 + n0],     W1[(k0 + 9) * 512 + n0]);
        v.z = pk2f(W1[k0 * 512 + n0 + 8],       W1[(k0 + 1) * 512 + n0 + 8]);
        v.w = pk2f(W1[(k0 + 8) * 512 + n0 + 8], W1[(k0 + 9) * 512 + n0 + 8]);
        g_W1F[j] = v;
    } else {
        int j2 = j - 16 * 32 * 32;
        if (j2 < 32 * 8 * 32) {
            int S    = j2 >> 8;
            int q    = (j2 >> 5) & 7;
            int lane = j2 & 31;
            int k0 = S * 16 + (lane & 3) * 2;
            int n0 = q * 16 + (lane >> 2);
            uint4 v;
            v.x = pk2f(W2[k0 * 128 + n0],           W2[(k0 + 1) * 128 + n0]);
            v.y = pk2f(W2[(k0 + 8) * 128 + n0],     W2[(k0 + 9) * 128 + n0]);
            v.z = pk2f(W2[k0 * 128 + n0 + 8],       W2[(k0 + 1) * 128 + n0 + 8]);
            v.w = pk2f(W2[(k0 + 8) * 128 + n0 + 8], W2[(k0 + 9) * 128 + n0 + 8]);
            g_W2F[j2] = v;
        }
    }
}

__device__ __forceinline__ void ldsm_x4(uint32_t r[4], const __half* p) {
    uint32_t addr = (uint32_t)__cvta_generic_to_shared(p);
    asm volatile("ldmatrix.sync.aligned.m8n8.x4.shared.b16 {%0,%1,%2,%3}, [%4];"
                 : "=r"(r[0]), "=r"(r[1]), "=r"(r[2]), "=r"(r[3])
                 : "r"(addr));
}

__device__ __forceinline__ void mma16816(float c[4], const uint32_t a[4],
                                         uint32_t b0, uint32_t b1) {
    asm volatile(
        "mma.sync.aligned.m16n8k16.row.col.f32.f16.f16.f32 "
        "{%0,%1,%2,%3}, {%4,%5,%6,%7}, {%8,%9}, {%0,%1,%2,%3};"
        : "+f"(c[0]), "+f"(c[1]), "+f"(c[2]), "+f"(c[3])
        : "r"(a[0]), "r"(a[1]), "r"(a[2]), "r"(a[3]), "r"(b0), "r"(b1));
}

__global__ void __launch_bounds__(THREADS, 1)
extractor_mlp_kernel(const int* __restrict__ edge_index,
                     const float* __restrict__ b1,
                     const float* __restrict__ b2,
                     const float* __restrict__ W3,
                     const float* __restrict__ b3,
                     float* __restrict__ out, int E)
{
    extern __shared__ char smem[];
    __half* f12 = (__half*)smem;                           // [128][LDF]
    __half* x1b[2] = { (__half*)(smem + SZ_F12),           // [128][LDX] x2
                       (__half*)(smem + SZ_F12 + SZ_X1H) };

    __shared__ int   s_col[M_TILE];
    __shared__ int   s_row[M_TILE];
    __shared__ float b1s[512];
    __shared__ float b2s[128];
    __shared__ float W3s[128];
    __shared__ float sred[4 * 128];

    const int tid  = threadIdx.x;
    const int lane = tid & 31;
    const int w    = tid >> 5;        // 0..15
    const int wm   = (w & 3) * 32;    // M offset
    const int wn   = (w >> 2) * 32;   // N offset within 128-chunk
    const int wnp  = wn >> 4;         // n16-pair base
    const int base = blockIdx.x * M_TILE;

    // ---- indices + biases ------------------------------------------------
    if (tid < M_TILE) {
        int e = base + tid;
        s_col[tid] = (e < E) ? edge_index[e] : 0;
        s_row[tid] = (e < E) ? edge_index[E + e] : 0;
    } else if (tid < 2 * M_TILE) {
        int n = tid - M_TILE;
        b2s[n] = b2[n];
        W3s[n] = W3[n];
    }
    b1s[tid] = b1[tid];
    __syncthreads();

    // ---- gather f12 (already half) -----------------------------------------
    for (int i = tid; i < M_TILE * 32; i += THREADS) {
        int m = i >> 5;
        int q = i & 31;                  // uint4 group within 256-half row
        int idx = (q < 16) ? s_col[m] : s_row[m];
        int qq  = (q < 16) ? q : (q - 16);
        uint4 v = ((const uint4*)(g_embh + (long long)idx * 128))[qq];
        *(uint4*)(f12 + m * LDF + q * 8) = v;
    }
    __syncthreads();

    float acc2[2][4][4];
    #pragma unroll
    for (int mt = 0; mt < 2; ++mt)
        #pragma unroll
        for (int t8 = 0; t8 < 4; ++t8)
            #pragma unroll
            for (int r = 0; r < 4; ++r)
                acc2[mt][t8][r] = 0.0f;

    const int rowA = wm + (lane & 15);
    const int colA = (lane >> 4) * 8;
    const int g    = lane >> 2;
    const int cp   = (lane & 3) * 2;

    #pragma unroll 1
    for (int c = 0; c < 4; ++c) {
        __half* x1h = x1b[c & 1];

        // ----- layer 1: acc1 = f12 @ W1[:, c*128 + wn .. +32] ---------------
        float acc1[2][4][4];
        #pragma unroll
        for (int mt = 0; mt < 2; ++mt)
            #pragma unroll
            for (int t8 = 0; t8 < 4; ++t8)
                #pragma unroll
                for (int r = 0; r < 4; ++r)
                    acc1[mt][t8][r] = 0.0f;

        {
            const uint4* Wp = g_W1F + (c * 8 + wnp) * 32 + lane;   // ks stride: 32*32
            uint4 B0 = Wp[0];
            uint4 B1 = Wp[32];
            #pragma unroll 4
            for (int ks = 0; ks < 16; ++ks) {
                uint32_t a0[4], a1[4];
                ldsm_x4(a0, f12 + rowA * LDF + ks * 16 + colA);
                ldsm_x4(a1, f12 + (rowA + 16) * LDF + ks * 16 + colA);
                uint4 nB0, nB1;
                if (ks < 15) {
                    nB0 = Wp[(ks + 1) * 1024];
                    nB1 = Wp[(ks + 1) * 1024 + 32];
                }
                mma16816(acc1[0][0], a0, B0.x, B0.y);
                mma16816(acc1[0][1], a0, B0.z, B0.w);
                mma16816(acc1[0][2], a0, B1.x, B1.y);
                mma16816(acc1[0][3], a0, B1.z, B1.w);
                mma16816(acc1[1][0], a1, B0.x, B0.y);
                mma16816(acc1[1][1], a1, B0.z, B0.w);
                mma16816(acc1[1][2], a1, B1.x, B1.y);
                mma16816(acc1[1][3], a1, B1.z, B1.w);
                B0 = nB0; B1 = nB1;
            }
        }

        // ----- bias + relu in registers, store half2 to x1h -----------------
        #pragma unroll
        for (int t8 = 0; t8 < 4; ++t8) {
            int col = wn + t8 * 8 + cp;
            float bx = b1s[c * 128 + col];
            float by = b1s[c * 128 + col + 1];
            #pragma unroll
            for (int mt = 0; mt < 2; ++mt) {
                int ra = wm + mt * 16 + g;
                float r0 = fmaxf(acc1[mt][t8][0] + bx, 0.0f);
                float r1 = fmaxf(acc1[mt][t8][1] + by, 0.0f);
                float r2 = fmaxf(acc1[mt][t8][2] + bx, 0.0f);
                float r3 = fmaxf(acc1[mt][t8][3] + by, 0.0f);
                *(uint32_t*)(x1h + ra * LDX + col)       = pk2f(r0, r1);
                *(uint32_t*)(x1h + (ra + 8) * LDX + col) = pk2f(r2, r3);
            }
        }
        __syncthreads();   // RAW: x1h chunk visible to all (also serves WAR for c-2)

        // ----- layer 2 partial: acc2 += x1_c @ W2[c*128 .. , wn .. +32] -----
        {
            const uint4* Wp = g_W2F + ((c * 8) * 8 + wnp) * 32 + lane;  // ks stride: 8*32
            uint4 C0 = Wp[0];
            uint4 C1 = Wp[32];
            #pragma unroll 4
            for (int ks = 0; ks < 8; ++ks) {
                uint32_t a0[4], a1[4];
                ldsm_x4(a0, x1h + rowA * LDX + ks * 16 + colA);
                ldsm_x4(a1, x1h + (rowA + 16) * LDX + ks * 16 + colA);
                uint4 nC0, nC1;
                if (ks < 7) {
                    nC0 = Wp[(ks + 1) * 256];
                    nC1 = Wp[(ks + 1) * 256 + 32];
                }
                mma16816(acc2[0][0], a0, C0.x, C0.y);
                mma16816(acc2[0][1], a0, C0.z, C0.w);
                mma16816(acc2[0][2], a0, C1.x, C1.y);
                mma16816(acc2[0][3], a0, C1.z, C1.w);
                mma16816(acc2[1][0], a1, C0.x, C0.y);
                mma16816(acc2[1][1], a1, C0.z, C0.w);
                mma16816(acc2[1][2], a1, C1.x, C1.y);
                mma16816(acc2[1][3], a1, C1.z, C1.w);
                C0 = nC0; C1 = nC1;
            }
        }
    }

    // ---- layer 3 in registers: s = relu(x2 + b2) . W3 ----------------------
    #pragma unroll
    for (int mt = 0; mt < 2; ++mt) {
        float sA = 0.0f, sB = 0.0f;
        #pragma unroll
        for (int t8 = 0; t8 < 4; ++t8) {
            int col = wn + t8 * 8 + cp;
            float bx = b2s[col],     wx = W3s[col];
            float by = b2s[col + 1], wy = W3s[col + 1];
            sA += fmaxf(acc2[mt][t8][0] + bx, 0.0f) * wx
                + fmaxf(acc2[mt][t8][1] + by, 0.0f) * wy;
            sB += fmaxf(acc2[mt][t8][2] + bx, 0.0f) * wx
                + fmaxf(acc2[mt][t8][3] + by, 0.0f) * wy;
        }
        sA += __shfl_xor_sync(0xffffffffu, sA, 1);
        sA += __shfl_xor_sync(0xffffffffu, sA, 2);
        sB += __shfl_xor_sync(0xffffffffu, sB, 1);
        sB += __shfl_xor_sync(0xffffffffu, sB, 2);
        if ((lane & 3) == 0) {
            int r = wm + mt * 16 + g;
            sred[(w >> 2) * 128 + r]     = sA;
            sred[(w >> 2) * 128 + r + 8] = sB;
        }
    }
    __syncthreads();

    if (tid < M_TILE) {
        float v = sred[tid] + sred[128 + tid] + sred[256 + tid] + sred[384 + tid]
                + __ldg(b3);
        int e = base + tid;
        if (e < E) out[e] = v;
    }
}

extern "C" void kernel_launch(void* const* d_in, const int* in_sizes, int n_in,
                              void* d_out, int out_size)
{
    const float* emb = (const float*)d_in[0];
    const int*   ei  = (const int*)d_in[1];     // int32 (JAX x64 disabled)
    const float* W1  = (const float*)d_in[2];
    const float* b1  = (const float*)d_in[3];
    const float* W2  = (const float*)d_in[4];
    const float* b2  = (const float*)d_in[5];
    const float* W3  = (const float*)d_in[6];
    const float* b3  = (const float*)d_in[7];
    float* out = (float*)d_out;

    const int E  = out_size;             // output is [E,1] float32
    const int n4 = in_sizes[0] / 4;      // emb float4 count

    prep_emb<<<(n4 + 255) / 256, 256>>>(emb, n4);
    prep_weights<<<(16*32*32 + 32*8*32 + 255) / 256, 256>>>(W1, W2);

    cudaFuncSetAttribute(extractor_mlp_kernel,
                         cudaFuncAttributeMaxDynamicSharedMemorySize, SMEM_DYN);

    int grid = (E + M_TILE - 1) / M_TILE;
    extractor_mlp_kernel<<<grid, THREADS, SMEM_DYN>>>(
        ei, b1, b2, W3, b3, out, E);
}

// round 11
// speedup vs baseline: 1.4856x; 1.0157x over previous
#include <cuda_runtime.h>
#include <cuda_fp16.h>
#include <cstdint>

// ---------------------------------------------------------------------------
// Fused ExtractorMLP, raw mma.sync.m16n8k16 (fp16 in, fp32 acc).
// Round 11 = round-10 + NAMED BARRIERS: x1h rows are private to an mg group
// (4 warps sharing the same 32 M-rows), so the main-loop syncs use
// bar.sync(mg+1, 128) instead of CTA-wide __syncthreads(). The four mg groups
// slide independently; barrier drains overlap other groups' MMA work.
// ---------------------------------------------------------------------------

#define M_TILE  128
#define THREADS 512
#define LDF 264          // f12 leading dim (halves): 528B stride, mod128=16
#define LDX 136          // x1h leading dim (halves): 272B stride, mod128=16
#define SZ_F12 (M_TILE * LDF * 2)
#define SZ_X1H (M_TILE * LDX * 2)
#define SMEM_DYN (SZ_F12 + 2 * SZ_X1H)

#define N_NODES_MAX 50000

__device__ __half g_embh[N_NODES_MAX * 128];   // 12.8 MB
// fragment-packed weights (B operand order for mma.m16n8k16)
__device__ uint4 g_W1F[16 * 32 * 32];   // 256 KB
__device__ uint4 g_W2F[32 * 8 * 32];    // 128 KB

__device__ __forceinline__ uint32_t pk2f(float a, float b) {
    __half2 h = __floats2half2_rn(a, b);
    return *reinterpret_cast<uint32_t*>(&h);
}

__global__ void prep_emb(const float* __restrict__ emb, int n4) {
    int i = blockIdx.x * blockDim.x + threadIdx.x;
    if (i < n4) {
        float4 v = ((const float4*)emb)[i];
        uint2 o;
        o.x = pk2f(v.x, v.y);
        o.y = pk2f(v.z, v.w);
        ((uint2*)g_embh)[i] = o;
    }
}

__global__ void prep_weights(const float* __restrict__ W1,
                             const float* __restrict__ W2) {
    int j = blockIdx.x * blockDim.x + threadIdx.x;
    if (j < 16 * 32 * 32) {
        int s    = j >> 10;
        int p    = (j >> 5) & 31;
        int lane = j & 31;
        int k0 = s * 16 + (lane & 3) * 2;
        int n0 = p * 16 + (lane >> 2);
        uint4 v;
        v.x = pk2f(W1[k0 * 512 + n0],           W1[(k0 + 1) * 512 + n0]);
        v.y = pk2f(W1[(k0 + 8) * 512 + n0],     W1[(k0 + 9) * 512 + n0]);
        v.z = pk2f(W1[k0 * 512 + n0 + 8],       W1[(k0 + 1) * 512 + n0 + 8]);
        v.w = pk2f(W1[(k0 + 8) * 512 + n0 + 8], W1[(k0 + 9) * 512 + n0 + 8]);
        g_W1F[j] = v;
    } else {
        int j2 = j - 16 * 32 * 32;
        if (j2 < 32 * 8 * 32) {
            int S    = j2 >> 8;
            int q    = (j2 >> 5) & 7;
            int lane = j2 & 31;
            int k0 = S * 16 + (lane & 3) * 2;
            int n0 = q * 16 + (lane >> 2);
            uint4 v;
            v.x = pk2f(W2[k0 * 128 + n0],           W2[(k0 + 1) * 128 + n0]);
            v.y = pk2f(W2[(k0 + 8) * 128 + n0],     W2[(k0 + 9) * 128 + n0]);
            v.z = pk2f(W2[k0 * 128 + n0 + 8],       W2[(k0 + 1) * 128 + n0 + 8]);
            v.w = pk2f(W2[(k0 + 8) * 128 + n0 + 8], W2[(k0 + 9) * 128 + n0 + 8]);
            g_W2F[j2] = v;
        }
    }
}

__device__ __forceinline__ void ldsm_x4(uint32_t r[4], const __half* p) {
    uint32_t addr = (uint32_t)__cvta_generic_to_shared(p);
    asm volatile("ldmatrix.sync.aligned.m8n8.x4.shared.b16 {%0,%1,%2,%3}, [%4];"
                 : "=r"(r[0]), "=r"(r[1]), "=r"(r[2]), "=r"(r[3])
                 : "r"(addr));
}

__device__ __forceinline__ void mma16816(float c[4], const uint32_t a[4],
                                         uint32_t b0, uint32_t b1) {
    asm volatile(
        "mma.sync.aligned.m16n8k16.row.col.f32.f16.f16.f32 "
        "{%0,%1,%2,%3}, {%4,%5,%6,%7}, {%8,%9}, {%0,%1,%2,%3};"
        : "+f"(c[0]), "+f"(c[1]), "+f"(c[2]), "+f"(c[3])
        : "r"(a[0]), "r"(a[1]), "r"(a[2]), "r"(a[3]), "r"(b0), "r"(b1));
}

__device__ __forceinline__ void group_bar(int id) {
    asm volatile("bar.sync %0, 128;" :: "r"(id) : "memory");
}

__global__ void __launch_bounds__(THREADS, 1)
extractor_mlp_kernel(const int* __restrict__ edge_index,
                     const float* __restrict__ b1,
                     const float* __restrict__ b2,
                     const float* __restrict__ W3,
                     const float* __restrict__ b3,
                     float* __restrict__ out, int E)
{
    extern __shared__ char smem[];
    __half* f12 = (__half*)smem;                           // [128][LDF]
    __half* x1b[2] = { (__half*)(smem + SZ_F12),           // [128][LDX] x2
                       (__half*)(smem + SZ_F12 + SZ_X1H) };

    __shared__ int   s_col[M_TILE];
    __shared__ int   s_row[M_TILE];
    __shared__ float b1s[512];
    __shared__ float b2s[128];
    __shared__ float W3s[128];
    __shared__ float sred[4 * 128];

    const int tid  = threadIdx.x;
    const int lane = tid & 31;
    const int w    = tid >> 5;        // 0..15
    const int mg   = w & 3;           // M group (rows mg*32 .. +32)
    const int wm   = mg * 32;
    const int wn   = (w >> 2) * 32;   // N offset within 128-chunk
    const int wnp  = wn >> 4;         // n16-pair base
    const int base = blockIdx.x * M_TILE;

    // ---- indices + biases ------------------------------------------------
    if (tid < M_TILE) {
        int e = base + tid;
        s_col[tid] = (e < E) ? edge_index[e] : 0;
        s_row[tid] = (e < E) ? edge_index[E + e] : 0;
    } else if (tid < 2 * M_TILE) {
        int n = tid - M_TILE;
        b2s[n] = b2[n];
        W3s[n] = W3[n];
    }
    b1s[tid] = b1[tid];
    __syncthreads();

    // ---- gather f12 (already half) -----------------------------------------
    for (int i = tid; i < M_TILE * 32; i += THREADS) {
        int m = i >> 5;
        int q = i & 31;                  // uint4 group within 256-half row
        int idx = (q < 16) ? s_col[m] : s_row[m];
        int qq  = (q < 16) ? q : (q - 16);
        uint4 v = ((const uint4*)(g_embh + (long long)idx * 128))[qq];
        *(uint4*)(f12 + m * LDF + q * 8) = v;
    }
    __syncthreads();

    float acc2[2][4][4];
    #pragma unroll
    for (int mt = 0; mt < 2; ++mt)
        #pragma unroll
        for (int t8 = 0; t8 < 4; ++t8)
            #pragma unroll
            for (int r = 0; r < 4; ++r)
                acc2[mt][t8][r] = 0.0f;

    const int rowA = wm + (lane & 15);
    const int colA = (lane >> 4) * 8;
    const int g    = lane >> 2;
    const int cp   = (lane & 3) * 2;

    #pragma unroll 1
    for (int c = 0; c < 4; ++c) {
        __half* x1h = x1b[c & 1];

        // ----- layer 1: acc1 = f12 @ W1[:, c*128 + wn .. +32] ---------------
        float acc1[2][4][4];
        #pragma unroll
        for (int mt = 0; mt < 2; ++mt)
            #pragma unroll
            for (int t8 = 0; t8 < 4; ++t8)
                #pragma unroll
                for (int r = 0; r < 4; ++r)
                    acc1[mt][t8][r] = 0.0f;

        {
            const uint4* Wp = g_W1F + (c * 8 + wnp) * 32 + lane;   // ks stride: 1024
            uint4 B0 = Wp[0];
            uint4 B1 = Wp[32];
            #pragma unroll 4
            for (int ks = 0; ks < 16; ++ks) {
                uint32_t a0[4], a1[4];
                ldsm_x4(a0, f12 + rowA * LDF + ks * 16 + colA);
                ldsm_x4(a1, f12 + (rowA + 16) * LDF + ks * 16 + colA);
                uint4 nB0, nB1;
                if (ks < 15) {
                    nB0 = Wp[(ks + 1) * 1024];
                    nB1 = Wp[(ks + 1) * 1024 + 32];
                }
                mma16816(acc1[0][0], a0, B0.x, B0.y);
                mma16816(acc1[0][1], a0, B0.z, B0.w);
                mma16816(acc1[0][2], a0, B1.x, B1.y);
                mma16816(acc1[0][3], a0, B1.z, B1.w);
                mma16816(acc1[1][0], a1, B0.x, B0.y);
                mma16816(acc1[1][1], a1, B0.z, B0.w);
                mma16816(acc1[1][2], a1, B1.x, B1.y);
                mma16816(acc1[1][3], a1, B1.z, B1.w);
                B0 = nB0; B1 = nB1;
            }
        }

        // ----- bias + relu in registers, store half2 to x1h -----------------
        #pragma unroll
        for (int t8 = 0; t8 < 4; ++t8) {
            int col = wn + t8 * 8 + cp;
            float bx = b1s[c * 128 + col];
            float by = b1s[c * 128 + col + 1];
            #pragma unroll
            for (int mt = 0; mt < 2; ++mt) {
                int ra = wm + mt * 16 + g;
                float r0 = fmaxf(acc1[mt][t8][0] + bx, 0.0f);
                float r1 = fmaxf(acc1[mt][t8][1] + by, 0.0f);
                float r2 = fmaxf(acc1[mt][t8][2] + bx, 0.0f);
                float r3 = fmaxf(acc1[mt][t8][3] + by, 0.0f);
                *(uint32_t*)(x1h + ra * LDX + col)       = pk2f(r0, r1);
                *(uint32_t*)(x1h + (ra + 8) * LDX + col) = pk2f(r2, r3);
            }
        }
        // x1h rows are mg-group private: sync only the 4 warps of this group.
        group_bar(1 + mg);

        // ----- layer 2 partial: acc2 += x1_c @ W2[c*128 .. , wn .. +32] -----
        {
            const uint4* Wp = g_W2F + ((c * 8) * 8 + wnp) * 32 + lane;  // ks stride: 256
            uint4 C0 = Wp[0];
            uint4 C1 = Wp[32];
            #pragma unroll 4
            for (int ks = 0; ks < 8; ++ks) {
                uint32_t a0[4], a1[4];
                ldsm_x4(a0, x1h + rowA * LDX + ks * 16 + colA);
                ldsm_x4(a1, x1h + (rowA + 16) * LDX + ks * 16 + colA);
                uint4 nC0, nC1;
                if (ks < 7) {
                    nC0 = Wp[(ks + 1) * 256];
                    nC1 = Wp[(ks + 1) * 256 + 32];
                }
                mma16816(acc2[0][0], a0, C0.x, C0.y);
                mma16816(acc2[0][1], a0, C0.z, C0.w);
                mma16816(acc2[0][2], a0, C1.x, C1.y);
                mma16816(acc2[0][3], a0, C1.z, C1.w);
                mma16816(acc2[1][0], a1, C0.x, C0.y);
                mma16816(acc2[1][1], a1, C0.z, C0.w);
                mma16816(acc2[1][2], a1, C1.x, C1.y);
                mma16816(acc2[1][3], a1, C1.z, C1.w);
                C0 = nC0; C1 = nC1;
            }
        }
    }

    // ---- layer 3 in registers: s = relu(x2 + b2) . W3 ----------------------
    #pragma unroll
    for (int mt = 0; mt < 2; ++mt) {
        float sA = 0.0f, sB = 0.0f;
        #pragma unroll
        for (int t8 = 0; t8 < 4; ++t8) {
            int col = wn + t8 * 8 + cp;
            float bx = b2s[col],     wx = W3s[col];
            float by = b2s[col + 1], wy = W3s[col + 1];
            sA += fmaxf(acc2[mt][t8][0] + bx, 0.0f) * wx
                + fmaxf(acc2[mt][t8][1] + by, 0.0f) * wy;
            sB += fmaxf(acc2[mt][t8][2] + bx, 0.0f) * wx
                + fmaxf(acc2[mt][t8][3] + by, 0.0f) * wy;
        }
        sA += __shfl_xor_sync(0xffffffffu, sA, 1);
        sA += __shfl_xor_sync(0xffffffffu, sA, 2);
        sB += __shfl_xor_sync(0xffffffffu, sB, 1);
        sB += __shfl_xor_sync(0xffffffffu, sB, 2);
        if ((lane & 3) == 0) {
            int r = wm + mt * 16 + g;
            sred[(w >> 2) * 128 + r]     = sA;
            sred[(w >> 2) * 128 + r + 8] = sB;
        }
    }
    __syncthreads();

    if (tid < M_TILE) {
        float v = sred[tid] + sred[128 + tid] + sred[256 + tid] + sred[384 + tid]
                + __ldg(b3);
        int e = base + tid;
        if (e < E) out[e] = v;
    }
}

extern "C" void kernel_launch(void* const* d_in, const int* in_sizes, int n_in,
                              void* d_out, int out_size)
{
    const float* emb = (const float*)d_in[0];
    const int*   ei  = (const int*)d_in[1];     // int32 (JAX x64 disabled)
    const float* W1  = (const float*)d_in[2];
    const float* b1  = (const float*)d_in[3];
    const float* W2  = (const float*)d_in[4];
    const float* b2  = (const float*)d_in[5];
    const float* W3  = (const float*)d_in[6];
    const float* b3  = (const float*)d_in[7];
    float* out = (float*)d_out;

    const int E  = out_size;             // output is [E,1] float32
    const int n4 = in_sizes[0] / 4;      // emb float4 count

    prep_emb<<<(n4 + 255) / 256, 256>>>(emb, n4);
    prep_weights<<<(16*32*32 + 32*8*32 + 255) / 256, 256>>>(W1, W2);

    cudaFuncSetAttribute(extractor_mlp_kernel,
                         cudaFuncAttributeMaxDynamicSharedMemorySize, SMEM_DYN);

    int grid = (E + M_TILE - 1) / M_TILE;
    extractor_mlp_kernel<<<grid, THREADS, SMEM_DYN>>>(
        ei, b1, b2, W3, b3, out, E);
}

// round 12
// speedup vs baseline: 1.9545x; 1.3156x over previous
#include <cuda_runtime.h>
#include <cuda_fp16.h>
#include <cstdint>

// ---------------------------------------------------------------------------
// Round 12: hoist layer 1 to a per-NODE precompute (nodes 50K << edges 800K).
//   hgen:  H[n][0:512]    = emb[n] @ W1[0:128,:]   + b1      (fp16)
//          H[n][512:1024] = emb[n] @ W1[128:256,:]           (fp16)
//   main:  x1 = relu(H[col][0:512] + H[row][512:1024])       (gather+add)
//          x2 = relu(x1 @ W2 + b2); out = x2 @ W3 + b3       (mma.m16n8k16)
// Layer-1 edge-side MMAs (2/3 of FLOPs) are eliminated.
// ---------------------------------------------------------------------------

#define THREADS 512
#define M_TILE  128
#define N_NODES_MAX 50048

#define LDH 520   // x1s leading dim (halves): 1040B stride, mod128=16
#define LDE 136   // hgen emb tile leading dim (halves): 272B, mod128=16

__device__ __half g_H[(size_t)N_NODES_MAX * 1024];   // ~102.5 MB
__device__ uint4  g_WcatF[8 * 64 * 32];              // W1-cat B fragments
__device__ uint4  g_W2F[32 * 8 * 32];                // W2 B fragments

__device__ __forceinline__ uint32_t pk2f(float a, float b) {
    __half2 h = __floats2half2_rn(a, b);
    return *reinterpret_cast<uint32_t*>(&h);
}

// Wcat[k][j] (k<128, j<1024): j<512 ? W1[k][j] : W1[128+k][j-512]
__device__ __forceinline__ float wcat(const float* W1, int k, int j) {
    return (j < 512) ? W1[k * 512 + j] : W1[(128 + k) * 512 + (j - 512)];
}

__global__ void prep_weights(const float* __restrict__ W1,
                             const float* __restrict__ W2) {
    int j = blockIdx.x * blockDim.x + threadIdx.x;
    if (j < 8 * 64 * 32) {
        int ks   = j >> 11;          // 0..7
        int p    = (j >> 5) & 63;    // n16-pair 0..63
        int lane = j & 31;
        int k0 = ks * 16 + (lane & 3) * 2;
        int n0 = p * 16 + (lane >> 2);
        uint4 v;
        v.x = pk2f(wcat(W1, k0,     n0),     wcat(W1, k0 + 1, n0));
        v.y = pk2f(wcat(W1, k0 + 8, n0),     wcat(W1, k0 + 9, n0));
        v.z = pk2f(wcat(W1, k0,     n0 + 8), wcat(W1, k0 + 1, n0 + 8));
        v.w = pk2f(wcat(W1, k0 + 8, n0 + 8), wcat(W1, k0 + 9, n0 + 8));
        g_WcatF[j] = v;
    } else {
        int j2 = j - 8 * 64 * 32;
        if (j2 < 32 * 8 * 32) {
            int S    = j2 >> 8;
            int q    = (j2 >> 5) & 7;
            int lane = j2 & 31;
            int k0 = S * 16 + (lane & 3) * 2;
            int n0 = q * 16 + (lane >> 2);
            uint4 v;
            v.x = pk2f(W2[k0 * 128 + n0],           W2[(k0 + 1) * 128 + n0]);
            v.y = pk2f(W2[(k0 + 8) * 128 + n0],     W2[(k0 + 9) * 128 + n0]);
            v.z = pk2f(W2[k0 * 128 + n0 + 8],       W2[(k0 + 1) * 128 + n0 + 8]);
            v.w = pk2f(W2[(k0 + 8) * 128 + n0 + 8], W2[(k0 + 9) * 128 + n0 + 8]);
            g_W2F[j2] = v;
        }
    }
}

__device__ __forceinline__ void ldsm_x4(uint32_t r[4], const __half* p) {
    uint32_t addr = (uint32_t)__cvta_generic_to_shared(p);
    asm volatile("ldmatrix.sync.aligned.m8n8.x4.shared.b16 {%0,%1,%2,%3}, [%4];"
                 : "=r"(r[0]), "=r"(r[1]), "=r"(r[2]), "=r"(r[3])
                 : "r"(addr));
}

__device__ __forceinline__ void mma16816(float c[4], const uint32_t a[4],
                                         uint32_t b0, uint32_t b1) {
    asm volatile(
        "mma.sync.aligned.m16n8k16.row.col.f32.f16.f16.f32 "
        "{%0,%1,%2,%3}, {%4,%5,%6,%7}, {%8,%9}, {%0,%1,%2,%3};"
        : "+f"(c[0]), "+f"(c[1]), "+f"(c[2]), "+f"(c[3])
        : "r"(a[0]), "r"(a[1]), "r"(a[2]), "r"(a[3]), "r"(b0), "r"(b1));
}

// ---------------- hgen: per-node layer-1 table --------------------------
__global__ void __launch_bounds__(THREADS, 1)
hgen_kernel(const float* __restrict__ emb, const float* __restrict__ b1,
            int n_nodes)
{
    extern __shared__ char smem[];
    __half* embt  = (__half*)smem;                       // [128][LDE]
    __half* stage = (__half*)(smem + 128 * LDE * 2);     // [128][LDE]
    __shared__ float b1s[512];

    const int tid  = threadIdx.x;
    const int lane = tid & 31;
    const int w    = tid >> 5;
    const int wm   = (w & 3) * 32;
    const int wn   = (w >> 2) * 32;
    const int wnp  = wn >> 4;
    const int base = blockIdx.x * 128;

    b1s[tid] = b1[tid];

    // load emb tile (fp32 -> half)
    for (int i = tid; i < 128 * 32; i += THREADS) {
        int r = i >> 5, q = i & 31;
        int node = base + r;
        float4 v = (node < n_nodes) ? ((const float4*)(emb + (size_t)node * 128))[q]
                                    : make_float4(0.f, 0.f, 0.f, 0.f);
        uint32_t* dst = (uint32_t*)(embt + r * LDE + q * 4);
        dst[0] = pk2f(v.x, v.y);
        dst[1] = pk2f(v.z, v.w);
    }
    __syncthreads();

    const int rowA = wm + (lane & 15);
    const int colA = (lane >> 4) * 8;
    const int g    = lane >> 2;
    const int cp   = (lane & 3) * 2;

    #pragma unroll 1
    for (int c = 0; c < 8; ++c) {
        float acc[2][4][4];
        #pragma unroll
        for (int mt = 0; mt < 2; ++mt)
            #pragma unroll
            for (int t8 = 0; t8 < 4; ++t8)
                #pragma unroll
                for (int r = 0; r < 4; ++r)
                    acc[mt][t8][r] = 0.0f;

        const uint4* Wp = g_WcatF + (c * 8 + wnp) * 32 + lane;  // ks stride 2048
        uint4 B0 = Wp[0];
        uint4 B1 = Wp[32];
        #pragma unroll
        for (int ks = 0; ks < 8; ++ks) {
            uint32_t a0[4], a1[4];
            ldsm_x4(a0, embt + rowA * LDE + ks * 16 + colA);
            ldsm_x4(a1, embt + (rowA + 16) * LDE + ks * 16 + colA);
            uint4 nB0, nB1;
            if (ks < 7) {
                nB0 = Wp[(ks + 1) * 2048];
                nB1 = Wp[(ks + 1) * 2048 + 32];
            }
            mma16816(acc[0][0], a0, B0.x, B0.y);
            mma16816(acc[0][1], a0, B0.z, B0.w);
            mma16816(acc[0][2], a0, B1.x, B1.y);
            mma16816(acc[0][3], a0, B1.z, B1.w);
            mma16816(acc[1][0], a1, B0.x, B0.y);
            mma16816(acc[1][1], a1, B0.z, B0.w);
            mma16816(acc[1][2], a1, B1.x, B1.y);
            mma16816(acc[1][3], a1, B1.z, B1.w);
            B0 = nB0; B1 = nB1;
        }

        // +b1 for the Hc half (c<4), no relu; pack half -> stage
        #pragma unroll
        for (int t8 = 0; t8 < 4; ++t8) {
            int col = wn + t8 * 8 + cp;
            float bx = (c < 4) ? b1s[c * 128 + col]     : 0.0f;
            float by = (c < 4) ? b1s[c * 128 + col + 1] : 0.0f;
            #pragma unroll
            for (int mt = 0; mt < 2; ++mt) {
                int ra = wm + mt * 16 + g;
                *(uint32_t*)(stage + ra * LDE + col) =
                    pk2f(acc[mt][t8][0] + bx, acc[mt][t8][1] + by);
                *(uint32_t*)(stage + (ra + 8) * LDE + col) =
                    pk2f(acc[mt][t8][2] + bx, acc[mt][t8][3] + by);
            }
        }
        __syncthreads();

        // coalesced copy stage -> g_H[node][c*128 ..]
        for (int i = tid; i < 128 * 16; i += THREADS) {
            int r = i >> 4, q = i & 15;
            int node = base + r;
            if (node < n_nodes)
                *(uint4*)(g_H + (size_t)node * 1024 + c * 128 + q * 8) =
                    *(uint4*)(stage + r * LDE + q * 8);
        }
        __syncthreads();
    }
}

// ---------------- main: gather+add+relu, layer-2 GEMM, epilogue ----------
__device__ __forceinline__ uint32_t addrelu2(uint32_t a, uint32_t b) {
    float2 fa = __half22float2(*(__half2*)&a);
    float2 fb = __half22float2(*(__half2*)&b);
    return pk2f(fmaxf(fa.x + fb.x, 0.0f), fmaxf(fa.y + fb.y, 0.0f));
}

__global__ void __launch_bounds__(THREADS, 1)
extractor_mlp_kernel(const int* __restrict__ edge_index,
                     const float* __restrict__ b2,
                     const float* __restrict__ W3,
                     const float* __restrict__ b3,
                     float* __restrict__ out, int E)
{
    extern __shared__ char smem[];
    __half* x1s = (__half*)smem;                 // [128][LDH]

    __shared__ int   s_col[M_TILE];
    __shared__ int   s_row[M_TILE];
    __shared__ float b2s[128];
    __shared__ float W3s[128];
    __shared__ float sred[4 * 128];

    const int tid  = threadIdx.x;
    const int lane = tid & 31;
    const int w    = tid >> 5;
    const int wm   = (w & 3) * 32;
    const int wn   = (w >> 2) * 32;
    const int wnp  = wn >> 4;
    const int base = blockIdx.x * M_TILE;

    if (tid < M_TILE) {
        int e = base + tid;
        s_col[tid] = (e < E) ? edge_index[e] : 0;
        s_row[tid] = (e < E) ? edge_index[E + e] : 0;
    } else if (tid < 2 * M_TILE) {
        int n = tid - M_TILE;
        b2s[n] = b2[n];
        W3s[n] = W3[n];
    }
    __syncthreads();

    // ---- phase 1: x1 = relu(Hc[col] + Hr[row])  (b1 folded into Hc) ------
    for (int i = tid; i < M_TILE * 64; i += THREADS) {
        int m = i >> 6;
        int q = i & 63;                          // uint4 index within 512 halves
        const __half* pc = g_H + (size_t)s_col[m] * 1024 + q * 8;
        const __half* pr = g_H + (size_t)s_row[m] * 1024 + 512 + q * 8;
        uint4 va = *(const uint4*)pc;
        uint4 vb = *(const uint4*)pr;
        uint4 o;
        o.x = addrelu2(va.x, vb.x);
        o.y = addrelu2(va.y, vb.y);
        o.z = addrelu2(va.z, vb.z);
        o.w = addrelu2(va.w, vb.w);
        *(uint4*)(x1s + m * LDH + q * 8) = o;
    }
    __syncthreads();

    // ---- phase 2: x2 = x1 @ W2 (k = 512, 32 k-steps) ----------------------
    float acc2[2][4][4];
    #pragma unroll
    for (int mt = 0; mt < 2; ++mt)
        #pragma unroll
        for (int t8 = 0; t8 < 4; ++t8)
            #pragma unroll
            for (int r = 0; r < 4; ++r)
                acc2[mt][t8][r] = 0.0f;

    const int rowA = wm + (lane & 15);
    const int colA = (lane >> 4) * 8;
    const int g    = lane >> 2;
    const int cp   = (lane & 3) * 2;

    {
        const uint4* Wp = g_W2F + wnp * 32 + lane;   // ks stride 256
        uint4 C0 = Wp[0];
        uint4 C1 = Wp[32];
        #pragma unroll 4
        for (int ks = 0; ks < 32; ++ks) {
            uint32_t a0[4], a1[4];
            ldsm_x4(a0, x1s + rowA * LDH + ks * 16 + colA);
            ldsm_x4(a1, x1s + (rowA + 16) * LDH + ks * 16 + colA);
            uint4 nC0, nC1;
            if (ks < 31) {
                nC0 = Wp[(ks + 1) * 256];
                nC1 = Wp[(ks + 1) * 256 + 32];
            }
            mma16816(acc2[0][0], a0, C0.x, C0.y);
            mma16816(acc2[0][1], a0, C0.z, C0.w);
            mma16816(acc2[0][2], a0, C1.x, C1.y);
            mma16816(acc2[0][3], a0, C1.z, C1.w);
            mma16816(acc2[1][0], a1, C0.x, C0.y);
            mma16816(acc2[1][1], a1, C0.z, C0.w);
            mma16816(acc2[1][2], a1, C1.x, C1.y);
            mma16816(acc2[1][3], a1, C1.z, C1.w);
            C0 = nC0; C1 = nC1;
        }
    }

    // ---- layer 3 in registers: s = relu(x2 + b2) . W3 ----------------------
    #pragma unroll
    for (int mt = 0; mt < 2; ++mt) {
        float sA = 0.0f, sB = 0.0f;
        #pragma unroll
        for (int t8 = 0; t8 < 4; ++t8) {
            int col = wn + t8 * 8 + cp;
            float bx = b2s[col],     wx = W3s[col];
            float by = b2s[col + 1], wy = W3s[col + 1];
            sA += fmaxf(acc2[mt][t8][0] + bx, 0.0f) * wx
                + fmaxf(acc2[mt][t8][1] + by, 0.0f) * wy;
            sB += fmaxf(acc2[mt][t8][2] + bx, 0.0f) * wx
                + fmaxf(acc2[mt][t8][3] + by, 0.0f) * wy;
        }
        sA += __shfl_xor_sync(0xffffffffu, sA, 1);
        sA += __shfl_xor_sync(0xffffffffu, sA, 2);
        sB += __shfl_xor_sync(0xffffffffu, sB, 1);
        sB += __shfl_xor_sync(0xffffffffu, sB, 2);
        if ((lane & 3) == 0) {
            int r = wm + mt * 16 + g;
            sred[(w >> 2) * 128 + r]     = sA;
            sred[(w >> 2) * 128 + r + 8] = sB;
        }
    }
    __syncthreads();

    if (tid < M_TILE) {
        float v = sred[tid] + sred[128 + tid] + sred[256 + tid] + sred[384 + tid]
                + __ldg(b3);
        int e = base + tid;
        if (e < E) out[e] = v;
    }
}

extern "C" void kernel_launch(void* const* d_in, const int* in_sizes, int n_in,
                              void* d_out, int out_size)
{
    const float* emb = (const float*)d_in[0];
    const int*   ei  = (const int*)d_in[1];     // int32 (JAX x64 disabled)
    const float* W1  = (const float*)d_in[2];
    const float* b1  = (const float*)d_in[3];
    const float* W2  = (const float*)d_in[4];
    const float* b2  = (const float*)d_in[5];
    const float* W3  = (const float*)d_in[6];
    const float* b3  = (const float*)d_in[7];
    float* out = (float*)d_out;

    const int E       = out_size;            // output is [E,1] float32
    int n_nodes       = in_sizes[0] / 128;   // emb is [N,128] float32
    if (n_nodes > N_NODES_MAX) n_nodes = N_NODES_MAX;

    prep_weights<<<(8*64*32 + 32*8*32 + 255) / 256, 256>>>(W1, W2);

    size_t hg_smem = (size_t)2 * 128 * LDE * 2;   // embt + stage
    cudaFuncSetAttribute(hgen_kernel,
                         cudaFuncAttributeMaxDynamicSharedMemorySize, (int)hg_smem);
    hgen_kernel<<<(n_nodes + 127) / 128, THREADS, hg_smem>>>(emb, b1, n_nodes);

    size_t mk_smem = (size_t)M_TILE * LDH * 2;    // x1s
    cudaFuncSetAttribute(extractor_mlp_kernel,
                         cudaFuncAttributeMaxDynamicSharedMemorySize, (int)mk_smem);
    int grid = (E + M_TILE - 1) / M_TILE;
    extractor_mlp_kernel<<<grid, THREADS, mk_smem>>>(ei, b2, W3, b3, out, E);
}

// round 13
// speedup vs baseline: 2.2425x; 1.1473x over previous
#include <cuda_runtime.h>
#include <cuda_fp16.h>
#include <cstdint>

// ---------------------------------------------------------------------------
// Round 13 = round-12 (layer-1 hoisted per node into fp16 table H) with the
// main kernel split into M_TILE=64 / 256-thread CTAs so TWO CTAs co-reside
// per SM: one CTA's gather/barrier/epilogue overlaps the other's layer-2
// MMAs. Gather add uses native half2 ops.
//   hgen:  H[n][0:512]    = emb[n]@W1_top + b1 ; H[n][512:1024] = emb[n]@W1_bot
//   main:  x1 = relu(H[col][lo] + H[row][hi]);  x2 = relu(x1@W2+b2); out = x2.W3+b3
// ---------------------------------------------------------------------------

#define THREADS 256
#define M_TILE  64
#define N_NODES_MAX 50048

#define LDH 520   // x1s leading dim (halves): 1040B stride, mod128=16
#define LDE 136   // hgen emb tile leading dim (halves): 272B, mod128=16

__device__ __half g_H[(size_t)N_NODES_MAX * 1024];   // ~102.5 MB
__device__ uint4  g_WcatF[8 * 64 * 32];              // W1-cat B fragments
__device__ uint4  g_W2F[32 * 8 * 32];                // W2 B fragments

__device__ __forceinline__ uint32_t pk2f(float a, float b) {
    __half2 h = __floats2half2_rn(a, b);
    return *reinterpret_cast<uint32_t*>(&h);
}

// Wcat[k][j] (k<128, j<1024): j<512 ? W1[k][j] : W1[128+k][j-512]
__device__ __forceinline__ float wcat(const float* W1, int k, int j) {
    return (j < 512) ? W1[k * 512 + j] : W1[(128 + k) * 512 + (j - 512)];
}

__global__ void prep_weights(const float* __restrict__ W1,
                             const float* __restrict__ W2) {
    int j = blockIdx.x * blockDim.x + threadIdx.x;
    if (j < 8 * 64 * 32) {
        int ks   = j >> 11;
        int p    = (j >> 5) & 63;
        int lane = j & 31;
        int k0 = ks * 16 + (lane & 3) * 2;
        int n0 = p * 16 + (lane >> 2);
        uint4 v;
        v.x = pk2f(wcat(W1, k0,     n0),     wcat(W1, k0 + 1, n0));
        v.y = pk2f(wcat(W1, k0 + 8, n0),     wcat(W1, k0 + 9, n0));
        v.z = pk2f(wcat(W1, k0,     n0 + 8), wcat(W1, k0 + 1, n0 + 8));
        v.w = pk2f(wcat(W1, k0 + 8, n0 + 8), wcat(W1, k0 + 9, n0 + 8));
        g_WcatF[j] = v;
    } else {
        int j2 = j - 8 * 64 * 32;
        if (j2 < 32 * 8 * 32) {
            int S    = j2 >> 8;
            int q    = (j2 >> 5) & 7;
            int lane = j2 & 31;
            int k0 = S * 16 + (lane & 3) * 2;
            int n0 = q * 16 + (lane >> 2);
            uint4 v;
            v.x = pk2f(W2[k0 * 128 + n0],           W2[(k0 + 1) * 128 + n0]);
            v.y = pk2f(W2[(k0 + 8) * 128 + n0],     W2[(k0 + 9) * 128 + n0]);
            v.z = pk2f(W2[k0 * 128 + n0 + 8],       W2[(k0 + 1) * 128 + n0 + 8]);
            v.w = pk2f(W2[(k0 + 8) * 128 + n0 + 8], W2[(k0 + 9) * 128 + n0 + 8]);
            g_W2F[j2] = v;
        }
    }
}

__device__ __forceinline__ void ldsm_x4(uint32_t r[4], const __half* p) {
    uint32_t addr = (uint32_t)__cvta_generic_to_shared(p);
    asm volatile("ldmatrix.sync.aligned.m8n8.x4.shared.b16 {%0,%1,%2,%3}, [%4];"
                 : "=r"(r[0]), "=r"(r[1]), "=r"(r[2]), "=r"(r[3])
                 : "r"(addr));
}

__device__ __forceinline__ void mma16816(float c[4], const uint32_t a[4],
                                         uint32_t b0, uint32_t b1) {
    asm volatile(
        "mma.sync.aligned.m16n8k16.row.col.f32.f16.f16.f32 "
        "{%0,%1,%2,%3}, {%4,%5,%6,%7}, {%8,%9}, {%0,%1,%2,%3};"
        : "+f"(c[0]), "+f"(c[1]), "+f"(c[2]), "+f"(c[3])
        : "r"(a[0]), "r"(a[1]), "r"(a[2]), "r"(a[3]), "r"(b0), "r"(b1));
}

// ---------------- hgen: per-node layer-1 table (512 threads) -------------
__global__ void __launch_bounds__(512, 1)
hgen_kernel(const float* __restrict__ emb, const float* __restrict__ b1,
            int n_nodes)
{
    extern __shared__ char smem[];
    __half* embt  = (__half*)smem;                       // [128][LDE]
    __half* stage = (__half*)(smem + 128 * LDE * 2);     // [128][LDE]
    __shared__ float b1s[512];

    const int tid  = threadIdx.x;
    const int lane = tid & 31;
    const int w    = tid >> 5;
    const int wm   = (w & 3) * 32;
    const int wn   = (w >> 2) * 32;
    const int wnp  = wn >> 4;
    const int base = blockIdx.x * 128;

    b1s[tid] = b1[tid];

    for (int i = tid; i < 128 * 32; i += 512) {
        int r = i >> 5, q = i & 31;
        int node = base + r;
        float4 v = (node < n_nodes) ? ((const float4*)(emb + (size_t)node * 128))[q]
                                    : make_float4(0.f, 0.f, 0.f, 0.f);
        uint32_t* dst = (uint32_t*)(embt + r * LDE + q * 4);
        dst[0] = pk2f(v.x, v.y);
        dst[1] = pk2f(v.z, v.w);
    }
    __syncthreads();

    const int rowA = wm + (lane & 15);
    const int colA = (lane >> 4) * 8;
    const int g    = lane >> 2;
    const int cp   = (lane & 3) * 2;

    #pragma unroll 1
    for (int c = 0; c < 8; ++c) {
        float acc[2][4][4];
        #pragma unroll
        for (int mt = 0; mt < 2; ++mt)
            #pragma unroll
            for (int t8 = 0; t8 < 4; ++t8)
                #pragma unroll
                for (int r = 0; r < 4; ++r)
                    acc[mt][t8][r] = 0.0f;

        const uint4* Wp = g_WcatF + (c * 8 + wnp) * 32 + lane;
        uint4 B0 = Wp[0];
        uint4 B1 = Wp[32];
        #pragma unroll
        for (int ks = 0; ks < 8; ++ks) {
            uint32_t a0[4], a1[4];
            ldsm_x4(a0, embt + rowA * LDE + ks * 16 + colA);
            ldsm_x4(a1, embt + (rowA + 16) * LDE + ks * 16 + colA);
            uint4 nB0, nB1;
            if (ks < 7) {
                nB0 = Wp[(ks + 1) * 2048];
                nB1 = Wp[(ks + 1) * 2048 + 32];
            }
            mma16816(acc[0][0], a0, B0.x, B0.y);
            mma16816(acc[0][1], a0, B0.z, B0.w);
            mma16816(acc[0][2], a0, B1.x, B1.y);
            mma16816(acc[0][3], a0, B1.z, B1.w);
            mma16816(acc[1][0], a1, B0.x, B0.y);
            mma16816(acc[1][1], a1, B0.z, B0.w);
            mma16816(acc[1][2], a1, B1.x, B1.y);
            mma16816(acc[1][3], a1, B1.z, B1.w);
            B0 = nB0; B1 = nB1;
        }

        #pragma unroll
        for (int t8 = 0; t8 < 4; ++t8) {
            int col = wn + t8 * 8 + cp;
            float bx = (c < 4) ? b1s[c * 128 + col]     : 0.0f;
            float by = (c < 4) ? b1s[c * 128 + col + 1] : 0.0f;
            #pragma unroll
            for (int mt = 0; mt < 2; ++mt) {
                int ra = wm + mt * 16 + g;
                *(uint32_t*)(stage + ra * LDE + col) =
                    pk2f(acc[mt][t8][0] + bx, acc[mt][t8][1] + by);
                *(uint32_t*)(stage + (ra + 8) * LDE + col) =
                    pk2f(acc[mt][t8][2] + bx, acc[mt][t8][3] + by);
            }
        }
        __syncthreads();

        for (int i = tid; i < 128 * 16; i += 512) {
            int r = i >> 4, q = i & 15;
            int node = base + r;
            if (node < n_nodes)
                *(uint4*)(g_H + (size_t)node * 1024 + c * 128 + q * 8) =
                    *(uint4*)(stage + r * LDE + q * 8);
        }
        __syncthreads();
    }
}

// ---------------- main: gather+add+relu, layer-2 GEMM, epilogue ----------
__device__ __forceinline__ uint32_t addrelu2(uint32_t a, uint32_t b) {
    __half2 ha = *(__half2*)&a;
    __half2 hb = *(__half2*)&b;
    __half2 z  = __floats2half2_rn(0.f, 0.f);
    __half2 r  = __hmax2(__hadd2(ha, hb), z);
    return *(uint32_t*)&r;
}

__global__ void __launch_bounds__(THREADS, 2)
extractor_mlp_kernel(const int* __restrict__ edge_index,
                     const float* __restrict__ b2,
                     const float* __restrict__ W3,
                     const float* __restrict__ b3,
                     float* __restrict__ out, int E)
{
    extern __shared__ char smem[];
    __half* x1s = (__half*)smem;                 // [64][LDH]

    __shared__ int   s_col[M_TILE];
    __shared__ int   s_row[M_TILE];
    __shared__ float b2s[128];
    __shared__ float W3s[128];
    __shared__ float sred[4 * M_TILE];

    const int tid  = threadIdx.x;
    const int lane = tid & 31;
    const int w    = tid >> 5;        // 0..7
    const int wm   = (w & 1) * 32;    // M offset (2 groups)
    const int wn   = (w >> 1) * 32;   // N offset (4 groups)
    const int wnp  = wn >> 4;
    const int base = blockIdx.x * M_TILE;

    if (tid < M_TILE) {
        int e = base + tid;
        s_col[tid] = (e < E) ? edge_index[e] : 0;
        s_row[tid] = (e < E) ? edge_index[E + e] : 0;
    } else if (tid < M_TILE + 128) {
        int n = tid - M_TILE;
        b2s[n] = b2[n];
        W3s[n] = W3[n];
    }
    __syncthreads();

    // ---- phase 1: x1 = relu(Hc[col] + Hr[row])  (b1 folded into Hc) ------
    for (int i = tid; i < M_TILE * 64; i += THREADS) {
        int m = i >> 6;
        int q = i & 63;                          // uint4 index within 512 halves
        const __half* pc = g_H + (size_t)s_col[m] * 1024 + q * 8;
        const __half* pr = g_H + (size_t)s_row[m] * 1024 + 512 + q * 8;
        uint4 va = *(const uint4*)pc;
        uint4 vb = *(const uint4*)pr;
        uint4 o;
        o.x = addrelu2(va.x, vb.x);
        o.y = addrelu2(va.y, vb.y);
        o.z = addrelu2(va.z, vb.z);
        o.w = addrelu2(va.w, vb.w);
        *(uint4*)(x1s + m * LDH + q * 8) = o;
    }
    __syncthreads();

    // ---- phase 2: x2 = x1 @ W2 (k = 512, 32 k-steps) ----------------------
    float acc2[2][4][4];
    #pragma unroll
    for (int mt = 0; mt < 2; ++mt)
        #pragma unroll
        for (int t8 = 0; t8 < 4; ++t8)
            #pragma unroll
            for (int r = 0; r < 4; ++r)
                acc2[mt][t8][r] = 0.0f;

    const int rowA = wm + (lane & 15);
    const int colA = (lane >> 4) * 8;
    const int g    = lane >> 2;
    const int cp   = (lane & 3) * 2;

    {
        const uint4* Wp = g_W2F + wnp * 32 + lane;   // ks stride 256
        uint4 C0 = Wp[0];
        uint4 C1 = Wp[32];
        #pragma unroll 4
        for (int ks = 0; ks < 32; ++ks) {
            uint32_t a0[4], a1[4];
            ldsm_x4(a0, x1s + rowA * LDH + ks * 16 + colA);
            ldsm_x4(a1, x1s + (rowA + 16) * LDH + ks * 16 + colA);
            uint4 nC0, nC1;
            if (ks < 31) {
                nC0 = Wp[(ks + 1) * 256];
                nC1 = Wp[(ks + 1) * 256 + 32];
            }
            mma16816(acc2[0][0], a0, C0.x, C0.y);
            mma16816(acc2[0][1], a0, C0.z, C0.w);
            mma16816(acc2[0][2], a0, C1.x, C1.y);
            mma16816(acc2[0][3], a0, C1.z, C1.w);
            mma16816(acc2[1][0], a1, C0.x, C0.y);
            mma16816(acc2[1][1], a1, C0.z, C0.w);
            mma16816(acc2[1][2], a1, C1.x, C1.y);
            mma16816(acc2[1][3], a1, C1.z, C1.w);
            C0 = nC0; C1 = nC1;
        }
    }

    // ---- layer 3 in registers: s = relu(x2 + b2) . W3 ----------------------
    #pragma unroll
    for (int mt = 0; mt < 2; ++mt) {
        float sA = 0.0f, sB = 0.0f;
        #pragma unroll
        for (int t8 = 0; t8 < 4; ++t8) {
            int col = wn + t8 * 8 + cp;
            float bx = b2s[col],     wx = W3s[col];
            float by = b2s[col + 1], wy = W3s[col + 1];
            sA += fmaxf(acc2[mt][t8][0] + bx, 0.0f) * wx
                + fmaxf(acc2[mt][t8][1] + by, 0.0f) * wy;
            sB += fmaxf(acc2[mt][t8][2] + bx, 0.0f) * wx
                + fmaxf(acc2[mt][t8][3] + by, 0.0f) * wy;
        }
        sA += __shfl_xor_sync(0xffffffffu, sA, 1);
        sA += __shfl_xor_sync(0xffffffffu, sA, 2);
        sB += __shfl_xor_sync(0xffffffffu, sB, 1);
        sB += __shfl_xor_sync(0xffffffffu, sB, 2);
        if ((lane & 3) == 0) {
            int r = wm + mt * 16 + g;
            sred[(w >> 1) * M_TILE + r]     = sA;
            sred[(w >> 1) * M_TILE + r + 8] = sB;
        }
    }
    __syncthreads();

    if (tid < M_TILE) {
        float v = sred[tid] + sred[M_TILE + tid] + sred[2 * M_TILE + tid]
                + sred[3 * M_TILE + tid] + __ldg(b3);
        int e = base + tid;
        if (e < E) out[e] = v;
    }
}

extern "C" void kernel_launch(void* const* d_in, const int* in_sizes, int n_in,
                              void* d_out, int out_size)
{
    const float* emb = (const float*)d_in[0];
    const int*   ei  = (const int*)d_in[1];     // int32 (JAX x64 disabled)
    const float* W1  = (const float*)d_in[2];
    const float* b1  = (const float*)d_in[3];
    const float* W2  = (const float*)d_in[4];
    const float* b2  = (const float*)d_in[5];
    const float* W3  = (const float*)d_in[6];
    const float* b3  = (const float*)d_in[7];
    float* out = (float*)d_out;

    const int E  = out_size;             // output is [E,1] float32
    int n_nodes  = in_sizes[0] / 128;    // emb is [N,128] float32
    if (n_nodes > N_NODES_MAX) n_nodes = N_NODES_MAX;

    prep_weights<<<(8*64*32 + 32*8*32 + 255) / 256, 256>>>(W1, W2);

    size_t hg_smem = (size_t)2 * 128 * LDE * 2;
    cudaFuncSetAttribute(hgen_kernel,
                         cudaFuncAttributeMaxDynamicSharedMemorySize, (int)hg_smem);
    hgen_kernel<<<(n_nodes + 127) / 128, 512, hg_smem>>>(emb, b1, n_nodes);

    size_t mk_smem = (size_t)M_TILE * LDH * 2;    // 66560 B -> 2 CTAs/SM
    cudaFuncSetAttribute(extractor_mlp_kernel,
                         cudaFuncAttributeMaxDynamicSharedMemorySize, (int)mk_smem);
    int grid = (E + M_TILE - 1) / M_TILE;
    extractor_mlp_kernel<<<grid, THREADS, mk_smem>>>(ei, b2, W3, b3, out, E);
}